// round 14
// baseline (speedup 1.0000x reference)
#include <cuda_runtime.h>
#include <cuda_bf16.h>
#include <cstdint>

// out_means[b][d] = mean[d][labels[b][d]]; out_log_vars[b][d] = log_var[d][labels[b][d]]
// B = 2097152, N_DOMAINS = 8, MAX_CONCEPTS = 64.
// d_out: [means B*8 f32][log_vars B*8 f32].
//
// R14 = R13 (best wall, 35.3us x3) with the LAST LSU tenant removed:
// labels arrive via ONE 8KB 1D TMA bulk load (gmem->smem, mbarrier) per CTA,
// issued by t0 before the table load so its latency overlaps table+barrier.
// Threads then read labels from smem (2x LDS.128). Both directions of the
// 192MB stream now ride the TMA path; L1tex only carries table+staging work.

#define N_DOMAINS 8
#define MAX_CONCEPTS 64
#define TAB (N_DOMAINS * MAX_CONCEPTS)   // 512
#define BLK 256

__global__ __launch_bounds__(BLK)
void concept_gauss_kernel(const int4* __restrict__ labels4,   // [B*2]
                          const float* __restrict__ mean,     // [512]
                          const float* __restrict__ log_var,  // [512]
                          float* __restrict__ out,            // [2*B*8]
                          int B)
{
    __shared__ float s_mean[TAB];
    __shared__ float s_var[TAB];
    __shared__ alignas(128) int4  s_lab[BLK * 2];            // 8 KB label tile
    __shared__ alignas(128) float st_mean[BLK * N_DOMAINS];  // 8 KB, 1KB/warp
    __shared__ alignas(128) float st_var[BLK * N_DOMAINS];   // 8 KB, 1KB/warp
    __shared__ alignas(8) uint64_t mbar;

    const int t = threadIdx.x;
    const int w = t >> 5;
    const int lane = t & 31;

    const long base = (long)blockIdx.x * BLK;
    const long b    = base + t;
    const bool full_block = (base + BLK) <= (long)B;

    uint32_t mbar_a;
    asm("{ .reg .u64 a; cvta.to.shared.u64 a, %1; cvt.u32.u64 %0, a; }"
        : "=r"(mbar_a) : "l"(&mbar));

    // ---- FIRST (t0): kick the 8KB label TMA load so its latency overlaps
    // the table load + barrier below.
    if (full_block && t == 0) {
        asm volatile("mbarrier.init.shared.b64 [%0], 1;"
                     :: "r"(mbar_a) : "memory");
        // Order generic-proxy init before async-proxy barrier use.
        asm volatile("fence.proxy.async.shared::cta;" ::: "memory");
        asm volatile("mbarrier.arrive.expect_tx.shared.b64 _, [%0], %1;"
                     :: "r"(mbar_a), "r"((uint32_t)(BLK * 32)) : "memory");
        uint32_t dst;
        asm("{ .reg .u64 a; cvta.to.shared.u64 a, %1; cvt.u32.u64 %0, a; }"
            : "=r"(dst) : "l"(s_lab));
        asm volatile(
            "cp.async.bulk.shared::cta.global.mbarrier::complete_tx::bytes "
            "[%0], [%1], %2, [%3];"
            :: "r"(dst), "l"(&labels4[2 * base]),
               "r"((uint32_t)(BLK * 32)), "r"(mbar_a) : "memory");
    }

    // ---- Table load (2 KB each) + CTA barrier (also orders mbar init).
    s_mean[t]       = __ldg(&mean[t]);
    s_mean[t + 256] = __ldg(&mean[t + 256]);
    s_var[t]        = __ldg(&log_var[t]);
    s_var[t + 256]  = __ldg(&log_var[t + 256]);
    __syncthreads();

    if (full_block) {
        // Wait for the label tile (phase 0; fresh smem every launch).
        {
            uint32_t done;
            asm volatile(
                "{\n\t"
                ".reg .pred p;\n\t"
                "mbarrier.try_wait.parity.acquire.cta.shared::cta.b64 p, [%1], 0;\n\t"
                "selp.b32 %0, 1, 0, p;\n\t"
                "}"
                : "=r"(done) : "r"(mbar_a) : "memory");
            if (!done) {
                asm volatile(
                    "{\n\t"
                    ".reg .pred P1;\n\t"
                    "LW_%=:\n\t"
                    "mbarrier.try_wait.parity.acquire.cta.shared::cta.b64 P1, [%0], 0, 0x989680;\n\t"
                    "@P1 bra.uni LD_%=;\n\t"
                    "bra.uni LW_%=;\n\t"
                    "LD_%=:\n\t"
                    "}"
                    :: "r"(mbar_a) : "memory");
            }
        }

        const int4 l0 = s_lab[2 * t];
        const int4 l1 = s_lab[2 * t + 1];

        float4* pm = reinterpret_cast<float4*>(&st_mean[t * N_DOMAINS]);
        float4* pv = reinterpret_cast<float4*>(&st_var[t * N_DOMAINS]);

        pm[0] = make_float4(s_mean[0 * MAX_CONCEPTS + l0.x],
                            s_mean[1 * MAX_CONCEPTS + l0.y],
                            s_mean[2 * MAX_CONCEPTS + l0.z],
                            s_mean[3 * MAX_CONCEPTS + l0.w]);
        pm[1] = make_float4(s_mean[4 * MAX_CONCEPTS + l1.x],
                            s_mean[5 * MAX_CONCEPTS + l1.y],
                            s_mean[6 * MAX_CONCEPTS + l1.z],
                            s_mean[7 * MAX_CONCEPTS + l1.w]);
        pv[0] = make_float4(s_var[0 * MAX_CONCEPTS + l0.x],
                            s_var[1 * MAX_CONCEPTS + l0.y],
                            s_var[2 * MAX_CONCEPTS + l0.z],
                            s_var[3 * MAX_CONCEPTS + l0.w]);
        pv[1] = make_float4(s_var[4 * MAX_CONCEPTS + l1.x],
                            s_var[5 * MAX_CONCEPTS + l1.y],
                            s_var[6 * MAX_CONCEPTS + l1.z],
                            s_var[7 * MAX_CONCEPTS + l1.w]);

        // Warp-local completion of this warp's 1KB staging slices.
        __syncwarp();

        if (lane == 0) {
            // Order this warp's generic-proxy STS before async-proxy TMA reads.
            asm volatile("fence.proxy.async.shared::cta;" ::: "memory");

            uint32_t sm_m, sm_v;
            asm("{ .reg .u64 a; cvta.to.shared.u64 a, %1; cvt.u32.u64 %0, a; }"
                : "=r"(sm_m) : "l"(&st_mean[w * 32 * N_DOMAINS]));
            asm("{ .reg .u64 a; cvta.to.shared.u64 a, %1; cvt.u32.u64 %0, a; }"
                : "=r"(sm_v) : "l"(&st_var[w * 32 * N_DOMAINS]));

            const uint32_t bytes = 32 * N_DOMAINS * sizeof(float);  // 1024
            float* dst_m = out + (base + w * 32) * N_DOMAINS;
            float* dst_v = out + (long)B * N_DOMAINS + (base + w * 32) * N_DOMAINS;

            asm volatile(
                "cp.async.bulk.global.shared::cta.bulk_group [%0], [%1], %2;"
                :: "l"(dst_m), "r"(sm_m), "r"(bytes) : "memory");
            asm volatile(
                "cp.async.bulk.global.shared::cta.bulk_group [%0], [%1], %2;"
                :: "l"(dst_v), "r"(sm_v), "r"(bytes) : "memory");
            asm volatile("cp.async.bulk.commit_group;" ::: "memory");
            // Wait only for TMA smem READ completion; lane 0's residency keeps
            // the CTA's smem alive, other lanes exit immediately.
            asm volatile("cp.async.bulk.wait_group.read 0;" ::: "memory");
        }
    } else {
        // Tail (unused for B = 2^21): direct LDG + direct stores.
        if (b < B) {
            int4 l0 = __ldcs(&labels4[2 * b]);
            int4 l1 = __ldcs(&labels4[2 * b + 1]);
            float4* o = reinterpret_cast<float4*>(out);
            long vb = 2L * B;  // float4 units
            o[2 * b]     = make_float4(s_mean[0 * MAX_CONCEPTS + l0.x],
                                       s_mean[1 * MAX_CONCEPTS + l0.y],
                                       s_mean[2 * MAX_CONCEPTS + l0.z],
                                       s_mean[3 * MAX_CONCEPTS + l0.w]);
            o[2 * b + 1] = make_float4(s_mean[4 * MAX_CONCEPTS + l1.x],
                                       s_mean[5 * MAX_CONCEPTS + l1.y],
                                       s_mean[6 * MAX_CONCEPTS + l1.z],
                                       s_mean[7 * MAX_CONCEPTS + l1.w]);
            o[vb + 2 * b]     = make_float4(s_var[0 * MAX_CONCEPTS + l0.x],
                                            s_var[1 * MAX_CONCEPTS + l0.y],
                                            s_var[2 * MAX_CONCEPTS + l0.z],
                                            s_var[3 * MAX_CONCEPTS + l0.w]);
            o[vb + 2 * b + 1] = make_float4(s_var[4 * MAX_CONCEPTS + l1.x],
                                            s_var[5 * MAX_CONCEPTS + l1.y],
                                            s_var[6 * MAX_CONCEPTS + l1.z],
                                            s_var[7 * MAX_CONCEPTS + l1.w]);
        }
    }
}

extern "C" void kernel_launch(void* const* d_in, const int* in_sizes, int n_in,
                              void* d_out, int out_size) {
    const int4*  labels4 = (const int4*)d_in[0];
    const float* mean    = (const float*)d_in[1];
    const float* log_var = (const float*)d_in[2];
    float* out = (float*)d_out;

    int B = in_sizes[0] / N_DOMAINS;   // 2097152
    int blocks = (B + BLK - 1) / BLK;  // 8192
    concept_gauss_kernel<<<blocks, BLK>>>(labels4, mean, log_var, out, B);
}

// round 15
// speedup vs baseline: 1.1486x; 1.1486x over previous
#include <cuda_runtime.h>
#include <cuda_bf16.h>
#include <cstdint>

// out_means[b][d] = mean[d][labels[b][d]]; out_log_vars[b][d] = log_var[d][labels[b][d]]
// B = 2097152, N_DOMAINS = 8, MAX_CONCEPTS = 64.
// d_out: [means B*8 f32][log_vars B*8 f32].
//
// FINAL KERNEL (R9 config; wall 35.296/35.296/35.328us, rel_err 0.0):
//  - 256 samples/CTA, 8192 CTAs
//  - 2x LDG.128 __ldcs label loads HOISTED above the table-load barrier
//    (their DRAM latency overlaps the table load + BAR; ptxas won't hoist
//    LDGs across BAR.SYNC itself)
//  - scalar f32 smem tables (bank-conflict degree <= 2; float2 fusion and
//    TMA label loads both measured worse)
//  - per-warp smem staging + 1KB TMA bulk stores issued after __syncwarp
//    (removes STG.128 issue cost from the LSU pipe, no second CTA barrier)
//  - cp.async.bulk.wait_group.read 0 (waits smem-READ completion only, not
//    global visibility) executed by lane 0 per warp; all other lanes exit —
//    lane 0's residency keeps the CTA's smem allocated until TMA is done
//  - no L2 cache policies (pinning either stream regressed wall)
//
// Measured at the memory-system floor: 192MB irreducible traffic at
// ~5.9TB/s combined; ncu pinned 31.7-33.9us across 8 structural variants.

#define N_DOMAINS 8
#define MAX_CONCEPTS 64
#define TAB (N_DOMAINS * MAX_CONCEPTS)   // 512
#define BLK 256

__global__ __launch_bounds__(BLK)
void concept_gauss_kernel(const int4* __restrict__ labels4,   // [B*2]
                          const float* __restrict__ mean,     // [512]
                          const float* __restrict__ log_var,  // [512]
                          float* __restrict__ out,            // [2*B*8]
                          int B)
{
    __shared__ float s_mean[TAB];
    __shared__ float s_var[TAB];
    __shared__ alignas(128) float st_mean[BLK * N_DOMAINS];  // 8 KB, 1KB/warp
    __shared__ alignas(128) float st_var[BLK * N_DOMAINS];   // 8 KB, 1KB/warp

    const int t = threadIdx.x;
    const int w = t >> 5;
    const int lane = t & 31;

    const long base = (long)blockIdx.x * BLK;
    const long b    = base + t;
    const bool full_block = (base + BLK) <= (long)B;
    const bool live = b < (long)B;

    // ---- FIRST: issue the label loads (no dependencies) so their DRAM
    // latency overlaps the table load + barrier below.
    int4 l0 = make_int4(0, 0, 0, 0), l1 = make_int4(0, 0, 0, 0);
    if (live) {
        l0 = __ldcs(&labels4[2 * b]);
        l1 = __ldcs(&labels4[2 * b + 1]);
    }

    // ---- Table load (2 KB each) + the only CTA-wide barrier.
    s_mean[t]       = __ldg(&mean[t]);
    s_mean[t + 256] = __ldg(&mean[t + 256]);
    s_var[t]        = __ldg(&log_var[t]);
    s_var[t + 256]  = __ldg(&log_var[t + 256]);
    __syncthreads();

    if (full_block) {
        float4* pm = reinterpret_cast<float4*>(&st_mean[t * N_DOMAINS]);
        float4* pv = reinterpret_cast<float4*>(&st_var[t * N_DOMAINS]);

        pm[0] = make_float4(s_mean[0 * MAX_CONCEPTS + l0.x],
                            s_mean[1 * MAX_CONCEPTS + l0.y],
                            s_mean[2 * MAX_CONCEPTS + l0.z],
                            s_mean[3 * MAX_CONCEPTS + l0.w]);
        pm[1] = make_float4(s_mean[4 * MAX_CONCEPTS + l1.x],
                            s_mean[5 * MAX_CONCEPTS + l1.y],
                            s_mean[6 * MAX_CONCEPTS + l1.z],
                            s_mean[7 * MAX_CONCEPTS + l1.w]);
        pv[0] = make_float4(s_var[0 * MAX_CONCEPTS + l0.x],
                            s_var[1 * MAX_CONCEPTS + l0.y],
                            s_var[2 * MAX_CONCEPTS + l0.z],
                            s_var[3 * MAX_CONCEPTS + l0.w]);
        pv[1] = make_float4(s_var[4 * MAX_CONCEPTS + l1.x],
                            s_var[5 * MAX_CONCEPTS + l1.y],
                            s_var[6 * MAX_CONCEPTS + l1.z],
                            s_var[7 * MAX_CONCEPTS + l1.w]);

        // Warp-local completion of this warp's 1KB staging slices.
        __syncwarp();

        if (lane == 0) {
            // Order this warp's generic-proxy STS before async-proxy TMA reads.
            asm volatile("fence.proxy.async.shared::cta;" ::: "memory");

            uint32_t sm_m, sm_v;
            asm("{ .reg .u64 a; cvta.to.shared.u64 a, %1; cvt.u32.u64 %0, a; }"
                : "=r"(sm_m) : "l"(&st_mean[w * 32 * N_DOMAINS]));
            asm("{ .reg .u64 a; cvta.to.shared.u64 a, %1; cvt.u32.u64 %0, a; }"
                : "=r"(sm_v) : "l"(&st_var[w * 32 * N_DOMAINS]));

            const uint32_t bytes = 32 * N_DOMAINS * sizeof(float);  // 1024
            float* dst_m = out + (base + w * 32) * N_DOMAINS;
            float* dst_v = out + (long)B * N_DOMAINS + (base + w * 32) * N_DOMAINS;

            asm volatile(
                "cp.async.bulk.global.shared::cta.bulk_group [%0], [%1], %2;"
                :: "l"(dst_m), "r"(sm_m), "r"(bytes) : "memory");
            asm volatile(
                "cp.async.bulk.global.shared::cta.bulk_group [%0], [%1], %2;"
                :: "l"(dst_v), "r"(sm_v), "r"(bytes) : "memory");
            asm volatile("cp.async.bulk.commit_group;" ::: "memory");
            // Wait only for TMA smem READ completion; lane 0's residency keeps
            // the CTA's smem alive, other lanes exit immediately.
            asm volatile("cp.async.bulk.wait_group.read 0;" ::: "memory");
        }
    } else {
        // Tail (unused for B = 2^21): direct stores.
        if (live) {
            float4* o = reinterpret_cast<float4*>(out);
            long vb = 2L * B;  // float4 units
            o[2 * b]     = make_float4(s_mean[0 * MAX_CONCEPTS + l0.x],
                                       s_mean[1 * MAX_CONCEPTS + l0.y],
                                       s_mean[2 * MAX_CONCEPTS + l0.z],
                                       s_mean[3 * MAX_CONCEPTS + l0.w]);
            o[2 * b + 1] = make_float4(s_mean[4 * MAX_CONCEPTS + l1.x],
                                       s_mean[5 * MAX_CONCEPTS + l1.y],
                                       s_mean[6 * MAX_CONCEPTS + l1.z],
                                       s_mean[7 * MAX_CONCEPTS + l1.w]);
            o[vb + 2 * b]     = make_float4(s_var[0 * MAX_CONCEPTS + l0.x],
                                            s_var[1 * MAX_CONCEPTS + l0.y],
                                            s_var[2 * MAX_CONCEPTS + l0.z],
                                            s_var[3 * MAX_CONCEPTS + l0.w]);
            o[vb + 2 * b + 1] = make_float4(s_var[4 * MAX_CONCEPTS + l1.x],
                                            s_var[5 * MAX_CONCEPTS + l1.y],
                                            s_var[6 * MAX_CONCEPTS + l1.z],
                                            s_var[7 * MAX_CONCEPTS + l1.w]);
        }
    }
}

extern "C" void kernel_launch(void* const* d_in, const int* in_sizes, int n_in,
                              void* d_out, int out_size) {
    const int4*  labels4 = (const int4*)d_in[0];
    const float* mean    = (const float*)d_in[1];
    const float* log_var = (const float*)d_in[2];
    float* out = (float*)d_out;

    int B = in_sizes[0] / N_DOMAINS;   // 2097152
    int blocks = (B + BLK - 1) / BLK;  // 8192
    concept_gauss_kernel<<<blocks, BLK>>>(labels4, mean, log_var, out, B);
}